// round 1
// baseline (speedup 1.0000x reference)
#include <cuda_runtime.h>

// ---------------------------------------------------------------------------
// LSTM_88244398063643
//   Phase 1: xW = x @ W + bias            (4096x1024 @ 1024x4096 fp32 GEMM)
//   Phase 2: sequential LSTM scan, persistent cooperative kernel,
//            U held in registers distributed across 128 blocks.
// Inputs (metadata order): x[4096*1024], W[1024*4096], U[1024*4096], bias[4096]
// Output: hidden_seq[4096*1024], then h_T[1024], c_T[1024] (guarded by out_size)
// ---------------------------------------------------------------------------

#define T_STEPS 4096
#define H_DIM   1024
#define I_DIM   1024
#define G4      4096   // 4*H

// Scratch (static device globals: allocation-free per harness rules)
__device__ float    g_xW[(size_t)T_STEPS * G4];   // 64 MB
__device__ float    g_hbuf[2][H_DIM];             // double-buffered h
__device__ unsigned g_bar_count;                  // grid barrier state
__device__ unsigned g_bar_sense;

// ============================ Phase 1: GEMM ================================
#define BM 128
#define BN 128
#define BK 8

__global__ __launch_bounds__(256) void gemm_xw_kernel(
    const float* __restrict__ A,      // x [4096,1024]
    const float* __restrict__ B,      // W [1024,4096]
    const float* __restrict__ bias)   // [4096]
{
    __shared__ float As[BK][BM];
    __shared__ float Bs[BK][BN];

    const int bx = blockIdx.x;        // N tile
    const int by = blockIdx.y;        // M tile
    const int tid = threadIdx.x;      // 0..255
    const int tx = tid & 15;          // 16 col groups of 8
    const int ty = tid >> 4;          // 16 row groups of 8

    float acc[8][8];
#pragma unroll
    for (int i = 0; i < 8; i++)
#pragma unroll
        for (int j = 0; j < 8; j++) acc[i][j] = 0.f;

    const int aRow = tid >> 1;            // 0..127
    const int aCol = (tid & 1) * 4;       // 0 or 4
    const int bRow = tid >> 5;            // 0..7
    const int bCol = (tid & 31) * 4;      // 0..124

    for (int k0 = 0; k0 < I_DIM; k0 += BK) {
        // load A tile (transposed into smem)
        float4 a4 = *(const float4*)(A + (size_t)(by * BM + aRow) * I_DIM + k0 + aCol);
        As[aCol + 0][aRow] = a4.x;
        As[aCol + 1][aRow] = a4.y;
        As[aCol + 2][aRow] = a4.z;
        As[aCol + 3][aRow] = a4.w;
        // load B tile
        *(float4*)&Bs[bRow][bCol] =
            *(const float4*)(B + (size_t)(k0 + bRow) * G4 + bx * BN + bCol);
        __syncthreads();

#pragma unroll
        for (int k = 0; k < BK; k++) {
            float4 a0 = *(const float4*)&As[k][ty * 8];
            float4 a1 = *(const float4*)&As[k][ty * 8 + 4];
            float4 b0 = *(const float4*)&Bs[k][tx * 8];
            float4 b1 = *(const float4*)&Bs[k][tx * 8 + 4];
            float ar[8] = {a0.x, a0.y, a0.z, a0.w, a1.x, a1.y, a1.z, a1.w};
            float br[8] = {b0.x, b0.y, b0.z, b0.w, b1.x, b1.y, b1.z, b1.w};
#pragma unroll
            for (int i = 0; i < 8; i++)
#pragma unroll
                for (int j = 0; j < 8; j++)
                    acc[i][j] = fmaf(ar[i], br[j], acc[i][j]);
        }
        __syncthreads();
    }

    // epilogue: += bias, write to g_xW
#pragma unroll
    for (int i = 0; i < 8; i++) {
        const size_t row = (size_t)(by * BM + ty * 8 + i);
        float* crow = g_xW + row * G4 + bx * BN + tx * 8;
        const float* brow = bias + bx * BN + tx * 8;
#pragma unroll
        for (int j = 0; j < 8; j++) crow[j] = acc[i][j] + brow[j];
    }
}

// ========================= Phase 2: recurrence =============================
#define NBLK   128
#define NTHR   512
#define NWARP  16
#define UNITS  8     // hidden units per block
#define KCHUNK 64    // K elements per warp

__global__ __launch_bounds__(NTHR, 1) void lstm_rec_kernel(
    const float* __restrict__ U,      // [1024, 4096] row-major
    float* __restrict__ out,
    long long out_size)
{
    __shared__ __align__(16) float hs[H_DIM];
    __shared__ float part[NWARP][33];   // padded

    const int tid  = threadIdx.x;
    const int wid  = tid >> 5;
    const int lane = tid & 31;
    const int blk  = blockIdx.x;

    // lane -> gate column mapping: lane = gate*8 + unit
    const int unit = lane & 7;
    const int gate = lane >> 3;
    const int gcol = gate * H_DIM + blk * UNITS + unit;

    // Load this thread's U slice into registers: U[wid*64 + i][gcol], i=0..63
    float Ur[KCHUNK];
    {
        const float* up = U + (size_t)(wid * KCHUNK) * G4 + gcol;
#pragma unroll
        for (int i = 0; i < KCHUNK; i++) Ur[i] = up[(size_t)i * G4];
    }

    unsigned local_sense = 0u;
    float c_state = 0.f;
    float h_last  = 0.f;

    for (int t = 0; t < T_STEPS; t++) {
        // --- load h_{t-1} into smem (zeros at t==0) ---
        if (t == 0) {
            hs[tid] = 0.f;
            hs[tid + NTHR] = 0.f;
        } else {
            const float* hb = g_hbuf[(t - 1) & 1];
            hs[tid] = hb[tid];
            hs[tid + NTHR] = hb[tid + NTHR];
        }
        // prefetch xW[t][gcol] early (latency hidden under the dot)
        float xw_val = 0.f;
        if (wid == 0) xw_val = g_xW[(size_t)t * G4 + gcol];
        __syncthreads();

        // --- dot: acc = sum_k U[gcol][k]*h[k] over this warp's K chunk ---
        float acc = 0.f;
        const float4* h4 = (const float4*)&hs[wid * KCHUNK];
#pragma unroll
        for (int i = 0; i < KCHUNK / 4; i++) {
            float4 h = h4[i];                     // broadcast across warp
            acc = fmaf(Ur[4 * i + 0], h.x, acc);
            acc = fmaf(Ur[4 * i + 1], h.y, acc);
            acc = fmaf(Ur[4 * i + 2], h.z, acc);
            acc = fmaf(Ur[4 * i + 3], h.w, acc);
        }
        part[wid][lane] = acc;
        __syncthreads();

        // --- warp 0: cross-warp reduce, activations, state update ---
        if (wid == 0) {
            float s = xw_val;
#pragma unroll
            for (int w = 0; w < NWARP; w++) s += part[w][lane];
            // lanes u,8+u,16+u,24+u hold i,f,g,o pre-activations of unit u
            float gi = s;
            float gf = __shfl_sync(0xffffffffu, s, lane + 8);
            float gg = __shfl_sync(0xffffffffu, s, lane + 16);
            float go = __shfl_sync(0xffffffffu, s, lane + 24);
            if (lane < 8) {
                float iv = 1.f / (1.f + __expf(-gi));
                float fv = 1.f / (1.f + __expf(-gf));
                float gv = tanhf(gg);
                float ov = 1.f / (1.f + __expf(-go));
                c_state = fv * c_state + iv * gv;
                float hv = ov * tanhf(c_state);
                h_last = hv;
                const int j = blk * UNITS + unit;
                g_hbuf[t & 1][j] = hv;
                out[(size_t)t * H_DIM + j] = hv;
            }
            __threadfence();   // make h_t visible before the barrier release
        }

        // --- grid barrier (sense-reversing; replay-safe: 4096 flips/launch) ---
        __syncthreads();
        if (tid == 0) {
            const unsigned ns = local_sense ^ 1u;
            if (atomicAdd(&g_bar_count, 1u) == NBLK - 1) {
                *(volatile unsigned*)&g_bar_count = 0u;
                __threadfence();
                *(volatile unsigned*)&g_bar_sense = ns;
            } else {
                while (*(volatile unsigned*)&g_bar_sense != ns) { }
            }
            __threadfence();
        }
        local_sense ^= 1u;
        __syncthreads();
    }

    // tail: h_T, c_T
    if ((size_t)out_size >= (size_t)T_STEPS * H_DIM + 2 * H_DIM) {
        if (wid == 0 && lane < 8) {
            const int j = blk * UNITS + unit;
            out[(size_t)T_STEPS * H_DIM + j] = h_last;
            out[(size_t)T_STEPS * H_DIM + H_DIM + j] = c_state;
        }
    }
}

// =============================== launch ====================================
extern "C" void kernel_launch(void* const* d_in, const int* in_sizes, int n_in,
                              void* d_out, int out_size)
{
    const float* x    = (const float*)d_in[0];
    const float* W    = (const float*)d_in[1];
    const float* U    = (const float*)d_in[2];
    const float* bias = (const float*)d_in[3];
    float* out = (float*)d_out;

    dim3 ggrid(G4 / BN, T_STEPS / BM);
    gemm_xw_kernel<<<ggrid, 256>>>(x, W, bias);

    lstm_rec_kernel<<<NBLK, NTHR>>>(U, out, (long long)out_size);
}